// round 9
// baseline (speedup 1.0000x reference)
#include <cuda_runtime.h>
#include <cuda_bf16.h>

#define DM   2048
#define DI   4096
#define MTOT 8192

// ---------------- scratch (device globals; runtime allocs forbidden) ------
// all activation/weight scratch is FP8 e4m3 (1 byte/elem)
__device__ __align__(128) unsigned char g_xn  [(size_t)MTOT * DM];
__device__ __align__(128) unsigned char g_win [(size_t)2 * DI * DM];
__device__ __align__(128) unsigned char g_wout[(size_t)DM * DI];   // pre-scaled by dtw*4096
__device__ __align__(128) unsigned char g_h   [(size_t)MTOT * DI];
__device__ float g_dtw[DI];

// ---------------- helpers --------------------------------------------------
__device__ __forceinline__ unsigned smem_u32(const void* p) {
    unsigned a;
    asm("{ .reg .u64 t; cvta.to.shared.u64 t, %1; cvt.u32.u64 %0, t; }" : "=r"(a) : "l"(p));
    return a;
}
__device__ __forceinline__ void cp16(unsigned s, const void* g) {
    asm volatile("cp.async.cg.shared.global [%0], [%1], 16;" :: "r"(s), "l"(g));
}
#define CP_COMMIT() asm volatile("cp.async.commit_group;" ::: "memory")
#define CP_WAIT(n)  asm volatile("cp.async.wait_group %0;" :: "n"(n) : "memory")

#define SWZ(o) ((unsigned)(o) ^ ((((unsigned)(o)) >> 3) & 0x70u))

__device__ __forceinline__ void ldsm4(unsigned (&r)[4], unsigned a) {
    asm volatile("ldmatrix.sync.aligned.m8n8.x4.shared.b16 {%0,%1,%2,%3}, [%4];"
        : "=r"(r[0]), "=r"(r[1]), "=r"(r[2]), "=r"(r[3]) : "r"(a));
}
__device__ __forceinline__ void ldsm2(unsigned (&r)[2], unsigned a) {
    asm volatile("ldmatrix.sync.aligned.m8n8.x2.shared.b16 {%0,%1}, [%2];"
        : "=r"(r[0]), "=r"(r[1]) : "r"(a));
}
// FP8 e4m3 MMA: m16n8k32, fp32 accumulate. Fragment byte-layout matches the
// bf16 k16 ldmatrix pattern exactly (16-byte k-chunks per 8-row matrix).
__device__ __forceinline__ void mma16832(float (&c)[4], const unsigned (&a)[4],
                                         const unsigned (&b)[2]) {
    asm volatile(
        "mma.sync.aligned.m16n8k32.row.col.f32.e4m3.e4m3.f32 "
        "{%0,%1,%2,%3}, {%4,%5,%6,%7}, {%8,%9}, {%0,%1,%2,%3};"
        : "+f"(c[0]), "+f"(c[1]), "+f"(c[2]), "+f"(c[3])
        : "r"(a[0]), "r"(a[1]), "r"(a[2]), "r"(a[3]), "r"(b[0]), "r"(b[1]));
}
// pack 4 fp32 -> 4 e4m3 bytes (memory order f0,f1,f2,f3)
__device__ __forceinline__ unsigned pk8(float f0, float f1, float f2, float f3) {
    unsigned short lo, hi;
    asm("cvt.rn.satfinite.e4m3x2.f32 %0, %1, %2;" : "=h"(lo) : "f"(f1), "f"(f0));
    asm("cvt.rn.satfinite.e4m3x2.f32 %0, %1, %2;" : "=h"(hi) : "f"(f3), "f"(f2));
    return (unsigned)lo | ((unsigned)hi << 16);
}
__device__ __forceinline__ unsigned short pk8x2(float f0, float f1) {
    unsigned short r;
    asm("cvt.rn.satfinite.e4m3x2.f32 %0, %1, %2;" : "=h"(r) : "f"(f1), "f"(f0));
    return r;
}
__device__ __forceinline__ float fsig(float v) {
    v = fminf(fmaxf(v, -15.f), 15.f);
    return 1.f / (1.f + __expf(-v));
}

// ---------------- prep kernels --------------------------------------------
__global__ void ln_kernel(const float* __restrict__ x,
                          const float* __restrict__ gamma,
                          const float* __restrict__ beta) {
    __shared__ float sred[16];
    __shared__ float s_mu, s_inv;
    int row = blockIdx.x, tid = threadIdx.x;
    const float4* xr = (const float4*)(x + (size_t)row * DM);
    float4 a = xr[tid], b = xr[tid + 256];
    float s = a.x + a.y + a.z + a.w + b.x + b.y + b.z + b.w;
    float q = a.x*a.x + a.y*a.y + a.z*a.z + a.w*a.w
            + b.x*b.x + b.y*b.y + b.z*b.z + b.w*b.w;
    for (int o = 16; o; o >>= 1) {
        s += __shfl_xor_sync(~0u, s, o);
        q += __shfl_xor_sync(~0u, q, o);
    }
    if ((tid & 31) == 0) { sred[tid >> 5] = s; sred[8 + (tid >> 5)] = q; }
    __syncthreads();
    if (tid == 0) {
        float S = 0.f, Q = 0.f;
        for (int i = 0; i < 8; i++) { S += sred[i]; Q += sred[8 + i]; }
        float mu = S / DM;
        s_mu = mu;
        s_inv = rsqrtf(Q / DM - mu * mu + 1e-5f);
    }
    __syncthreads();
    float mu = s_mu, inv = s_inv;
    float4 g0 = ((const float4*)gamma)[tid],       b0 = ((const float4*)beta)[tid];
    float4 g1 = ((const float4*)gamma)[tid + 256], b1 = ((const float4*)beta)[tid + 256];
    unsigned* dst = (unsigned*)(g_xn + (size_t)row * DM);
    dst[tid] = pk8((a.x - mu) * inv * g0.x + b0.x, (a.y - mu) * inv * g0.y + b0.y,
                   (a.z - mu) * inv * g0.z + b0.z, (a.w - mu) * inv * g0.w + b0.w);
    dst[tid + 256] = pk8((b.x - mu) * inv * g1.x + b1.x, (b.y - mu) * inv * g1.y + b1.y,
                         (b.z - mu) * inv * g1.z + b1.z, (b.w - mu) * inv * g1.w + b1.w);
}

__global__ void cvt_win_kernel(const float* __restrict__ src) {
    size_t i = (size_t)blockIdx.x * 256 + threadIdx.x;   // 8 elems / thread
    const float4* s = (const float4*)src;
    float4 f0 = s[2 * i], f1 = s[2 * i + 1];
    uint2 o;
    o.x = pk8(f0.x, f0.y, f0.z, f0.w);
    o.y = pk8(f1.x, f1.y, f1.z, f1.w);
    ((uint2*)g_win)[i] = o;
}

// W_out' = W_out * dtw * 4096  (dtw folded into GEMM2's K-weights; 4096 keeps
// values ~O(W_out) so e4m3 range is used; GEMM2 epilogue multiplies by 1/4096)
__global__ void cvt_wout_kernel(const float* __restrict__ src) {
    size_t i = (size_t)blockIdx.x * 256 + threadIdx.x;
    int c = (int)((i * 8) & (DI - 1));                   // column (= e index)
    const float4* s = (const float4*)src;
    float4 f0 = s[2 * i], f1 = s[2 * i + 1];
    uint2 o;
    o.x = pk8(f0.x * g_dtw[c]     * 4096.f, f0.y * g_dtw[c + 1] * 4096.f,
              f0.z * g_dtw[c + 2] * 4096.f, f0.w * g_dtw[c + 3] * 4096.f);
    o.y = pk8(f1.x * g_dtw[c + 4] * 4096.f, f1.y * g_dtw[c + 5] * 4096.f,
              f1.z * g_dtw[c + 6] * 4096.f, f1.w * g_dtw[c + 7] * 4096.f);
    ((uint2*)g_wout)[i] = o;
}

__global__ void dts_kernel(const float* __restrict__ dt) {
    __shared__ float red[32];
    __shared__ float s_m, s_s;
    int tid = threadIdx.x;
    float m = -1e30f;
    for (int i = tid; i < DI; i += 1024) m = fmaxf(m, -dt[i]);
    for (int o = 16; o; o >>= 1) m = fmaxf(m, __shfl_xor_sync(~0u, m, o));
    if ((tid & 31) == 0) red[tid >> 5] = m;
    __syncthreads();
    if (tid == 0) {
        float M = -1e30f;
        for (int i = 0; i < 32; i++) M = fmaxf(M, red[i]);
        s_m = M;
    }
    __syncthreads();
    float M = s_m, s = 0.f;
    for (int i = tid; i < DI; i += 1024) s += __expf(-dt[i] - M);
    for (int o = 16; o; o >>= 1) s += __shfl_xor_sync(~0u, s, o);
    if ((tid & 31) == 0) red[tid >> 5] = s;
    __syncthreads();
    if (tid == 0) {
        float S = 0.f;
        for (int i = 0; i < 32; i++) S += red[i];
        s_s = S;
    }
    __syncthreads();
    float inv = 1.f / s_s;
    for (int i = tid; i < DI; i += 1024) g_dtw[i] = __expf(-dt[i] - M) * inv;
}

// ---------------- FP8 mma.sync GEMMs --------------------------------------
// Tile rows are 128 BYTES = 128 fp8 elems (SW128 swizzle). Stage = 32 KB:
//   FUSED:  A[128x128B] @0, Bz[64x128B] @16K, Bg[64x128B] @24K   (K=128/stage)
//   !FUSED: A[128x128B] @0, B[128x128B] @16K
#define NSTAGE 3
#define STAGEB 32768u

// FUSED=true : h[128 x 64]-tile = z*sig(clamp z) * gc*sig(gc)   (fp8 out)
// FUSED=false: out[128 x 128]-tile = (h @ W_out'^T)/4096 + x
template <bool FUSED>
__global__ void __launch_bounds__(256)
gemm_kernel(const float* __restrict__ xres, float* __restrict__ out) {
    extern __shared__ char smem[];
    const unsigned sbase = smem_u32(smem);

    const int tid = threadIdx.x, wid = tid >> 5, lane = tid & 31;
    const int wm = wid & 1;          // 2 warp-rows (64 M each)
    const int wn = wid >> 1;         // 4 warp-cols
    const int m0 = blockIdx.y * 128;
    const int n0 = blockIdx.x * (FUSED ? 64 : 128);
    const int KIT = FUSED ? (DM / 128) : (DI / 128);
    const int ldA = FUSED ? DM : DI;                     // byte stride (1B/elem)
    const unsigned char* A  = FUSED ? g_xn : g_h;
    const unsigned char* B0 = FUSED ? g_win : g_wout;
    const unsigned char* B1 = g_win + (size_t)DI * DM;   // gate half of W_in

    float acc0[4][4][4];             // z (or out)
    float acc1[4][2][4];             // gate (fused only)
    #pragma unroll
    for (int mt = 0; mt < 4; mt++)
        #pragma unroll
        for (int nt = 0; nt < 4; nt++)
            #pragma unroll
            for (int j = 0; j < 4; j++) acc0[mt][nt][j] = 0.f;
    if (FUSED)
        #pragma unroll
        for (int mt = 0; mt < 4; mt++)
            #pragma unroll
            for (int nt = 0; nt < 2; nt++)
                #pragma unroll
                for (int j = 0; j < 4; j++) acc1[mt][nt][j] = 0.f;

    auto load_stage = [&](int s, int kb) {
        unsigned sb = sbase + (unsigned)s * STAGEB;
        int k0 = kb * 128;                               // byte offset in K
        #pragma unroll
        for (int i = tid; i < 2048; i += 256) {
            if (FUSED) {
                if (i < 1024) {            // A: 128 rows x 8 chunks
                    int r = i >> 3, c = i & 7;
                    cp16(sb + SWZ(r * 128 + c * 16),
                         A + (size_t)(m0 + r) * ldA + k0 + c * 16);
                } else if (i < 1536) {     // Bz: 64 rows
                    int j = i - 1024, r = j >> 3, c = j & 7;
                    cp16(sb + 16384u + SWZ(r * 128 + c * 16),
                         B0 + (size_t)(n0 + r) * DM + k0 + c * 16);
                } else {                   // Bg: 64 rows
                    int j = i - 1536, r = j >> 3, c = j & 7;
                    cp16(sb + 24576u + SWZ(r * 128 + c * 16),
                         B1 + (size_t)(n0 + r) * DM + k0 + c * 16);
                }
            } else {
                if (i < 1024) {            // A (h): 128 rows
                    int r = i >> 3, c = i & 7;
                    cp16(sb + SWZ(r * 128 + c * 16),
                         A + (size_t)(m0 + r) * ldA + k0 + c * 16);
                } else {                   // B (wout'): 128 rows
                    int j = i - 1024, r = j >> 3, c = j & 7;
                    cp16(sb + 16384u + SWZ(r * 128 + c * 16),
                         B0 + (size_t)(n0 + r) * DI + k0 + c * 16);
                }
            }
        }
        CP_COMMIT();
    };

    load_stage(0, 0);
    load_stage(1, 1);

    // per-lane ldmatrix address components (byte-based; fp8 k32 fragment ==
    // bf16 k16 fragment byte layout)
    const int arow = (lane & 7) + (lane & 8);        // 0..15
    const unsigned acsel = (lane >> 4) ? 16u : 0u;   // k-half select (bytes)
    const int brow = lane & 7;
    const unsigned bcsel = (lane & 8) ? 16u : 0u;

    for (int kb = 0; kb < KIT; kb++) {
        if (kb == KIT - 1) { CP_WAIT(0); } else { CP_WAIT(1); }
        __syncthreads();
        if (kb + 2 < KIT) load_stage((kb + 2) % NSTAGE, kb + 2);

        unsigned sb = sbase + (unsigned)(kb % NSTAGE) * STAGEB;
        unsigned sBz = sb + 16384u;
        unsigned sBg = sb + 24576u;
        #pragma unroll
        for (int kc = 0; kc < 4; kc++) {                 // 4 x k32 per 128B row
            unsigned a[4][4];
            #pragma unroll
            for (int mt = 0; mt < 4; mt++)
                ldsm4(a[mt], sb + SWZ((unsigned)((wm * 64 + mt * 16 + arow) * 128
                                                 + kc * 32) + acsel));
            if (FUSED) {
                #pragma unroll
                for (int nt = 0; nt < 2; nt++) {
                    unsigned bz[2], bg[2];
                    unsigned roff = (unsigned)((wn * 16 + nt * 8 + brow) * 128 + kc * 32);
                    ldsm2(bz, sBz + SWZ(roff + bcsel));
                    ldsm2(bg, sBg + SWZ(roff + bcsel));
                    #pragma unroll
                    for (int mt = 0; mt < 4; mt++) {
                        mma16832(acc0[mt][nt], a[mt], bz);
                        mma16832(acc1[mt][nt], a[mt], bg);
                    }
                }
            } else {
                #pragma unroll
                for (int nt = 0; nt < 4; nt++) {
                    unsigned b[2];
                    unsigned roff = (unsigned)((wn * 32 + nt * 8 + brow) * 128 + kc * 32);
                    ldsm2(b, sBz + SWZ(roff + bcsel));
                    #pragma unroll
                    for (int mt = 0; mt < 4; mt++)
                        mma16832(acc0[mt][nt], a[mt], b);
                }
            }
        }
        __syncthreads();
    }

    // ---------------- epilogue ---------------------------------------------
    const int mrow = (lane >> 2);
    const int ncol = (lane & 3) * 2;
    if (FUSED) {
        #pragma unroll
        for (int mt = 0; mt < 4; mt++)
            #pragma unroll
            for (int nt = 0; nt < 2; nt++) {
                int nl = wn * 16 + nt * 8 + ncol;
                #pragma unroll
                for (int h = 0; h < 2; h++) {
                    int m = m0 + wm * 64 + mt * 16 + mrow + h * 8;
                    float z0 = acc0[mt][nt][h * 2], z1 = acc0[mt][nt][h * 2 + 1];
                    float q0 = acc1[mt][nt][h * 2], q1 = acc1[mt][nt][h * 2 + 1];
                    float gc0 = fminf(fmaxf(q0, -15.f), 15.f);
                    float gc1 = fminf(fmaxf(q1, -15.f), 15.f);
                    float v0 = z0 * fsig(z0) * gc0 * fsig(gc0);
                    float v1 = z1 * fsig(z1) * gc1 * fsig(gc1);
                    *(unsigned short*)(g_h + (size_t)m * DI + n0 + nl) = pk8x2(v0, v1);
                }
            }
    } else {
        const float INV = 1.f / 4096.f;
        #pragma unroll
        for (int mt = 0; mt < 4; mt++)
            #pragma unroll
            for (int nt = 0; nt < 4; nt++) {
                int n = n0 + wn * 32 + nt * 8 + ncol;
                #pragma unroll
                for (int h = 0; h < 2; h++) {
                    int m = m0 + wm * 64 + mt * 16 + mrow + h * 8;
                    const float2 xv = *(const float2*)(xres + (size_t)m * DM + n);
                    float2 o;
                    o.x = acc0[mt][nt][h * 2]     * INV + xv.x;
                    o.y = acc0[mt][nt][h * 2 + 1] * INV + xv.y;
                    *(float2*)(out + (size_t)m * DM + n) = o;
                }
            }
    }
}

// ---------------- launch ----------------------------------------------------
extern "C" void kernel_launch(void* const* d_in, const int* in_sizes, int n_in,
                              void* d_out, int out_size) {
    const float* x     = (const float*)d_in[0];
    const float* gamma = (const float*)d_in[1];
    const float* beta  = (const float*)d_in[2];
    const float* W_in  = (const float*)d_in[3];
    const float* W_out = (const float*)d_in[4];
    const float* dt    = (const float*)d_in[5];
    float* out = (float*)d_out;

    ln_kernel<<<MTOT, 256>>>(x, gamma, beta);
    cvt_win_kernel<<<(int)((size_t)2 * DI * DM / 8 / 256), 256>>>(W_in);
    dts_kernel<<<1, 1024>>>(dt);
    cvt_wout_kernel<<<(int)((size_t)DM * DI / 8 / 256), 256>>>(W_out);

    const unsigned smem = NSTAGE * STAGEB;   // 96 KB
    static int attr_done = 0;
    if (!attr_done) {
        cudaFuncSetAttribute(gemm_kernel<true>,
                             cudaFuncAttributeMaxDynamicSharedMemorySize, smem);
        cudaFuncSetAttribute(gemm_kernel<false>,
                             cudaFuncAttributeMaxDynamicSharedMemorySize, smem);
        attr_done = 1;
    }
    gemm_kernel<true ><<<dim3(DI / 64, MTOT / 128), 256, smem>>>(nullptr, nullptr);
    gemm_kernel<false><<<dim3(DM / 128, MTOT / 128), 256, smem>>>(x, out);
}

// round 13
// speedup vs baseline: 1.0125x; 1.0125x over previous
#include <cuda_runtime.h>
#include <cuda_bf16.h>

#define DM   2048
#define DI   4096
#define MTOT 8192

// ---------------- scratch (device globals; runtime allocs forbidden) ------
__device__ __align__(128) __nv_bfloat16 g_xn  [(size_t)MTOT * DM];
__device__ __align__(128) __nv_bfloat16 g_win [(size_t)2 * DI * DM];
__device__ __align__(128) __nv_bfloat16 g_wout[(size_t)DM * DI];
__device__ __align__(128) __nv_bfloat16 g_h   [(size_t)MTOT * DI];
__device__ float g_dtw[DI];

// ---------------- helpers --------------------------------------------------
__device__ __forceinline__ unsigned smem_u32(const void* p) {
    unsigned a;
    asm("{ .reg .u64 t; cvta.to.shared.u64 t, %1; cvt.u32.u64 %0, t; }" : "=r"(a) : "l"(p));
    return a;
}
__device__ __forceinline__ void cp16(unsigned s, const void* g) {
    asm volatile("cp.async.cg.shared.global [%0], [%1], 16;" :: "r"(s), "l"(g));
}
#define CP_COMMIT() asm volatile("cp.async.commit_group;" ::: "memory")
#define CP_WAIT(n)  asm volatile("cp.async.wait_group %0;" :: "n"(n) : "memory")

#define SWZ(o) ((unsigned)(o) ^ ((((unsigned)(o)) >> 3) & 0x70u))

__device__ __forceinline__ void ldsm4(unsigned (&r)[4], unsigned a) {
    asm volatile("ldmatrix.sync.aligned.m8n8.x4.shared.b16 {%0,%1,%2,%3}, [%4];"
        : "=r"(r[0]), "=r"(r[1]), "=r"(r[2]), "=r"(r[3]) : "r"(a));
}
__device__ __forceinline__ void mma16816(float (&c)[4], const unsigned (&a)[4],
                                         unsigned b0, unsigned b1) {
    asm volatile(
        "mma.sync.aligned.m16n8k16.row.col.f32.bf16.bf16.f32 "
        "{%0,%1,%2,%3}, {%4,%5,%6,%7}, {%8,%9}, {%0,%1,%2,%3};"
        : "+f"(c[0]), "+f"(c[1]), "+f"(c[2]), "+f"(c[3])
        : "r"(a[0]), "r"(a[1]), "r"(a[2]), "r"(a[3]), "r"(b0), "r"(b1));
}
__device__ __forceinline__ unsigned pk2(float a, float b) {
    __nv_bfloat162 t = __floats2bfloat162_rn(a, b);
    return *reinterpret_cast<unsigned*>(&t);
}
__device__ __forceinline__ float fsig(float v) {
    v = fminf(fmaxf(v, -15.f), 15.f);
    return 1.f / (1.f + __expf(-v));
}

// ---------------- prep kernels --------------------------------------------
__global__ void ln_kernel(const float* __restrict__ x,
                          const float* __restrict__ gamma,
                          const float* __restrict__ beta) {
    __shared__ float sred[16];
    __shared__ float s_mu, s_inv;
    int row = blockIdx.x, tid = threadIdx.x;
    const float4* xr = (const float4*)(x + (size_t)row * DM);
    float4 a = xr[tid], b = xr[tid + 256];
    float s = a.x + a.y + a.z + a.w + b.x + b.y + b.z + b.w;
    float q = a.x*a.x + a.y*a.y + a.z*a.z + a.w*a.w
            + b.x*b.x + b.y*b.y + b.z*b.z + b.w*b.w;
    for (int o = 16; o; o >>= 1) {
        s += __shfl_xor_sync(~0u, s, o);
        q += __shfl_xor_sync(~0u, q, o);
    }
    if ((tid & 31) == 0) { sred[tid >> 5] = s; sred[8 + (tid >> 5)] = q; }
    __syncthreads();
    if (tid == 0) {
        float S = 0.f, Q = 0.f;
        for (int i = 0; i < 8; i++) { S += sred[i]; Q += sred[8 + i]; }
        float mu = S / DM;
        s_mu = mu;
        s_inv = rsqrtf(Q / DM - mu * mu + 1e-5f);
    }
    __syncthreads();
    float mu = s_mu, inv = s_inv;
    float4 g0 = ((const float4*)gamma)[tid],       b0 = ((const float4*)beta)[tid];
    float4 g1 = ((const float4*)gamma)[tid + 256], b1 = ((const float4*)beta)[tid + 256];
    unsigned* dst = (unsigned*)(g_xn + (size_t)row * DM);
    float nx = (a.x - mu) * inv * g0.x + b0.x, ny = (a.y - mu) * inv * g0.y + b0.y;
    float nz = (a.z - mu) * inv * g0.z + b0.z, nw = (a.w - mu) * inv * g0.w + b0.w;
    dst[tid * 2]     = pk2(nx, ny);
    dst[tid * 2 + 1] = pk2(nz, nw);
    nx = (b.x - mu) * inv * g1.x + b1.x; ny = (b.y - mu) * inv * g1.y + b1.y;
    nz = (b.z - mu) * inv * g1.z + b1.z; nw = (b.w - mu) * inv * g1.w + b1.w;
    dst[(tid + 256) * 2]     = pk2(nx, ny);
    dst[(tid + 256) * 2 + 1] = pk2(nz, nw);
}

__global__ void cvt_kernel(const float* __restrict__ src, int which, int n4) {
    __nv_bfloat16* dst = which ? g_win : g_wout;
    int i = blockIdx.x * blockDim.x + threadIdx.x;
    if (i < n4) {
        float4 f = ((const float4*)src)[i];
        uint2 o;
        o.x = pk2(f.x, f.y);
        o.y = pk2(f.z, f.w);
        ((uint2*)dst)[i] = o;
    }
}

__global__ void dts_kernel(const float* __restrict__ dt) {
    __shared__ float red[32];
    __shared__ float s_m, s_s;
    int tid = threadIdx.x;
    float m = -1e30f;
    for (int i = tid; i < DI; i += 1024) m = fmaxf(m, -dt[i]);
    for (int o = 16; o; o >>= 1) m = fmaxf(m, __shfl_xor_sync(~0u, m, o));
    if ((tid & 31) == 0) red[tid >> 5] = m;
    __syncthreads();
    if (tid == 0) {
        float M = -1e30f;
        for (int i = 0; i < 32; i++) M = fmaxf(M, red[i]);
        s_m = M;
    }
    __syncthreads();
    float M = s_m, s = 0.f;
    for (int i = tid; i < DI; i += 1024) s += __expf(-dt[i] - M);
    for (int o = 16; o; o >>= 1) s += __shfl_xor_sync(~0u, s, o);
    if ((tid & 31) == 0) red[tid >> 5] = s;
    __syncthreads();
    if (tid == 0) {
        float S = 0.f;
        for (int i = 0; i < 32; i++) S += red[i];
        s_s = S;
    }
    __syncthreads();
    float inv = 1.f / s_s;
    for (int i = tid; i < DI; i += 1024) g_dtw[i] = __expf(-dt[i] - M) * inv;
}

// ---------------- bf16 mma.sync GEMMs -------------------------------------
// Stage = 48 KB (BK = 64 elems = 128 B rows, SW128 swizzle):
//   A: 128 rows @0 (16 KB);  B: 256 rows @16384 (32 KB)
//     FUSED : B rows 0-127 = W_in z rows n0.., rows 128-255 = W_in gate rows
//     !FUSED: B rows = W_out rows n0..n0+255
// 3 stages (144 KB). One __syncthreads per k-iter: reads of stage (kb-1)%3
// complete before iteration kb's barrier; its overwrite (load of kb+2) is
// issued only after that barrier.
// ldmatrix k-half selector (+16 B) is applied INSIDE SWZ: pre-swizzle offsets
// have bit4==0, so the add is carry-free and the result stays inside the row.
#define NSTAGE 3
#define STAGEB 49152u

// FUSED=true : h[128 x 128] = z*sig(clamp z)*dtw * gc*sig(gc)   (bf16 out)
// FUSED=false: out[128 x 256] = h @ W_out^T + x                 (fp32 out)
template <bool FUSED>
__global__ void __launch_bounds__(256)
gemm_kernel(const float* __restrict__ xres, float* __restrict__ out) {
    extern __shared__ char smem[];
    const unsigned sbase = smem_u32(smem);
    __shared__ float s_dtw[128];

    const int tid = threadIdx.x, wid = tid >> 5, lane = tid & 31;
    const int wm = wid & 1;          // 2 warp-rows (64 M each)
    const int wn = wid >> 1;         // 4 warp-cols
    const int m0 = blockIdx.y * 128;
    const int n0 = blockIdx.x * (FUSED ? 128 : 256);
    const int KIT = FUSED ? (DM / 64) : (DI / 64);
    const int ldA = FUSED ? DM : DI;
    const __nv_bfloat16* A  = FUSED ? g_xn : g_h;
    const __nv_bfloat16* B0 = FUSED ? g_win : g_wout;
    const __nv_bfloat16* B1 = g_win + (size_t)DI * DM;   // gate half of W_in

    if (FUSED && tid < 128) s_dtw[tid] = g_dtw[n0 + tid];

    // acc[mt][nt]: FUSED nt 0-3 = z cols, nt 4-7 = gate cols; !FUSED nt 0-7 = out
    float acc[4][8][4];
    #pragma unroll
    for (int mt = 0; mt < 4; mt++)
        #pragma unroll
        for (int nt = 0; nt < 8; nt++)
            #pragma unroll
            for (int j = 0; j < 4; j++) acc[mt][nt][j] = 0.f;

    auto load_stage = [&](int s, int kb) {
        unsigned sb = sbase + (unsigned)s * STAGEB;
        int k0 = kb * 64;
        #pragma unroll
        for (int i = tid; i < 3072; i += 256) {
            if (i < 1024) {                       // A: 128 rows x 8 chunks
                int r = i >> 3, c = i & 7;
                cp16(sb + SWZ(r * 128 + c * 16),
                     A + (size_t)(m0 + r) * ldA + k0 + c * 8);
            } else {                              // B: 256 rows
                int j = i - 1024, r = j >> 3, c = j & 7;
                const __nv_bfloat16* src;
                if (FUSED)
                    src = (r < 128) ? (B0 + (size_t)(n0 + r) * DM)
                                    : (B1 + (size_t)(n0 + r - 128) * DM);
                else
                    src = B0 + (size_t)(n0 + r) * DI;
                cp16(sb + 16384u + SWZ(r * 128 + c * 16), src + k0 + c * 8);
            }
        }
        CP_COMMIT();
    };

    load_stage(0, 0);
    load_stage(1, 1);

    // ldmatrix lane-address components
    const int arow = (lane & 7) + (lane & 8);            // A: 16 rows
    const unsigned acsel = (unsigned)(lane >> 4) << 4;   // A: k-half (bytes, pre-swizzle)
    const int brow = (lane & 7) + ((lane >> 4) << 3);    // B: 16 rows (2 n-tiles)
    const unsigned bcsel = (unsigned)((lane >> 3) & 1) << 4;  // B: k-half (pre-swizzle)

    for (int kb = 0; kb < KIT; kb++) {
        if (kb == KIT - 1) { CP_WAIT(0); } else { CP_WAIT(1); }
        __syncthreads();
        if (kb + 2 < KIT) load_stage((kb + 2) % NSTAGE, kb + 2);

        unsigned sb = sbase + (unsigned)(kb % NSTAGE) * STAGEB;
        unsigned sB = sb + 16384u;
        #pragma unroll
        for (int kc = 0; kc < 4; kc++) {
            unsigned a[4][4];
            #pragma unroll
            for (int mt = 0; mt < 4; mt++)
                ldsm4(a[mt], sb + SWZ((unsigned)((wm * 64 + mt * 16 + arow) * 128
                                                 + kc * 32) + acsel));
            // bq[p] = {ntile(2p) k0, ntile(2p) k1, ntile(2p+1) k0, ntile(2p+1) k1}
            unsigned bq[4][4];
            if (FUSED) {
                #pragma unroll
                for (int p = 0; p < 2; p++)
                    ldsm4(bq[p], sB + SWZ((unsigned)((wn * 32 + p * 16 + brow) * 128
                                                     + kc * 32) + bcsel));
                #pragma unroll
                for (int p = 0; p < 2; p++)
                    ldsm4(bq[2 + p], sB + SWZ((unsigned)((128 + wn * 32 + p * 16 + brow) * 128
                                                         + kc * 32) + bcsel));
            } else {
                #pragma unroll
                for (int p = 0; p < 4; p++)
                    ldsm4(bq[p], sB + SWZ((unsigned)((wn * 64 + p * 16 + brow) * 128
                                                     + kc * 32) + bcsel));
            }
            #pragma unroll
            for (int mt = 0; mt < 4; mt++)
                #pragma unroll
                for (int nt = 0; nt < 8; nt++)
                    mma16816(acc[mt][nt], a[mt],
                             bq[nt >> 1][(nt & 1) * 2], bq[nt >> 1][(nt & 1) * 2 + 1]);
        }
    }

    // ---------------- epilogue ---------------------------------------------
    const int mrow = (lane >> 2);
    const int ncol = (lane & 3) * 2;
    if (FUSED) {
        #pragma unroll
        for (int mt = 0; mt < 4; mt++)
            #pragma unroll
            for (int nt = 0; nt < 4; nt++) {
                int nl = wn * 32 + nt * 8 + ncol;
                float w0 = s_dtw[nl], w1 = s_dtw[nl + 1];
                #pragma unroll
                for (int h = 0; h < 2; h++) {
                    int m = m0 + wm * 64 + mt * 16 + mrow + h * 8;
                    float z0 = acc[mt][nt][h * 2],     z1 = acc[mt][nt][h * 2 + 1];
                    float q0 = acc[mt][nt + 4][h * 2], q1 = acc[mt][nt + 4][h * 2 + 1];
                    float gc0 = fminf(fmaxf(q0, -15.f), 15.f);
                    float gc1 = fminf(fmaxf(q1, -15.f), 15.f);
                    float v0 = z0 * fsig(z0) * w0 * gc0 * fsig(gc0);
                    float v1 = z1 * fsig(z1) * w1 * gc1 * fsig(gc1);
                    *(unsigned*)(g_h + (size_t)m * DI + n0 + nl) = pk2(v0, v1);
                }
            }
    } else {
        #pragma unroll
        for (int mt = 0; mt < 4; mt++)
            #pragma unroll
            for (int nt = 0; nt < 8; nt++) {
                int n = n0 + wn * 64 + nt * 8 + ncol;
                #pragma unroll
                for (int h = 0; h < 2; h++) {
                    int m = m0 + wm * 64 + mt * 16 + mrow + h * 8;
                    const float2 xv = *(const float2*)(xres + (size_t)m * DM + n);
                    float2 o;
                    o.x = acc[mt][nt][h * 2]     + xv.x;
                    o.y = acc[mt][nt][h * 2 + 1] + xv.y;
                    *(float2*)(out + (size_t)m * DM + n) = o;
                }
            }
    }
}

// ---------------- launch ----------------------------------------------------
extern "C" void kernel_launch(void* const* d_in, const int* in_sizes, int n_in,
                              void* d_out, int out_size) {
    const float* x     = (const float*)d_in[0];
    const float* gamma = (const float*)d_in[1];
    const float* beta  = (const float*)d_in[2];
    const float* W_in  = (const float*)d_in[3];
    const float* W_out = (const float*)d_in[4];
    const float* dt    = (const float*)d_in[5];
    float* out = (float*)d_out;

    ln_kernel<<<MTOT, 256>>>(x, gamma, beta);
    {
        int n4 = 2 * DI * DM / 4;
        cvt_kernel<<<(n4 + 255) / 256, 256>>>(W_in, 1, n4);
    }
    {
        int n4 = DM * DI / 4;
        cvt_kernel<<<(n4 + 255) / 256, 256>>>(W_out, 0, n4);
    }
    dts_kernel<<<1, 1024>>>(dt);

    const unsigned smem = NSTAGE * STAGEB;   // 144 KB
    static int attr_done = 0;                 // never call attr-set during capture
    if (!attr_done) {
        cudaFuncSetAttribute(gemm_kernel<true>,
                             cudaFuncAttributeMaxDynamicSharedMemorySize, smem);
        cudaFuncSetAttribute(gemm_kernel<false>,
                             cudaFuncAttributeMaxDynamicSharedMemorySize, smem);
        attr_done = 1;
    }

    gemm_kernel<true ><<<dim3(DI / 128, MTOT / 128), 256, smem>>>(nullptr, nullptr);
    gemm_kernel<false><<<dim3(DM / 256, MTOT / 128), 256, smem>>>(x, out);
}

// round 14
// speedup vs baseline: 1.3223x; 1.3060x over previous
#include <cuda_runtime.h>
#include <cuda_fp16.h>

#define DM   2048
#define DI   4096
#define MTOT 8192

// h is stored scaled by 256 so GEMM2's fp16 products stay in normal range.
#define HSCALE 256.0f
#define HINV   (1.0f / 256.0f)

// ---------------- scratch (device globals; runtime allocs forbidden) ------
__device__ __align__(128) __half g_xn  [(size_t)MTOT * DM];
__device__ __align__(128) __half g_win [(size_t)2 * DI * DM];
__device__ __align__(128) __half g_wout[(size_t)DM * DI];
__device__ __align__(128) __half g_h   [(size_t)MTOT * DI];   // = 256 * true h
__device__ float g_dtw[DI];

// ---------------- helpers --------------------------------------------------
__device__ __forceinline__ unsigned smem_u32(const void* p) {
    unsigned a;
    asm("{ .reg .u64 t; cvta.to.shared.u64 t, %1; cvt.u32.u64 %0, t; }" : "=r"(a) : "l"(p));
    return a;
}
__device__ __forceinline__ void cp16(unsigned s, const void* g) {
    asm volatile("cp.async.cg.shared.global [%0], [%1], 16;" :: "r"(s), "l"(g));
}
#define CP_COMMIT() asm volatile("cp.async.commit_group;" ::: "memory")
#define CP_WAIT(n)  asm volatile("cp.async.wait_group %0;" :: "n"(n) : "memory")

#define SWZ(o) ((unsigned)(o) ^ ((((unsigned)(o)) >> 3) & 0x70u))

__device__ __forceinline__ void ldsm4(unsigned (&r)[4], unsigned a) {
    asm volatile("ldmatrix.sync.aligned.m8n8.x4.shared.b16 {%0,%1,%2,%3}, [%4];"
        : "=r"(r[0]), "=r"(r[1]), "=r"(r[2]), "=r"(r[3]) : "r"(a));
}
// fp16 MMA with fp16 accumulate: full-rate, 2 acc regs
__device__ __forceinline__ void mma16816h(unsigned (&c)[2], const unsigned (&a)[4],
                                          unsigned b0, unsigned b1) {
    asm volatile(
        "mma.sync.aligned.m16n8k16.row.col.f16.f16.f16.f16 "
        "{%0,%1}, {%2,%3,%4,%5}, {%6,%7}, {%0,%1};"
        : "+r"(c[0]), "+r"(c[1])
        : "r"(a[0]), "r"(a[1]), "r"(a[2]), "r"(a[3]), "r"(b0), "r"(b1));
}
__device__ __forceinline__ unsigned pk2h(float a, float b) {
    __half2 t = __floats2half2_rn(a, b);
    return *reinterpret_cast<unsigned*>(&t);
}
__device__ __forceinline__ float2 up2h(unsigned u) {
    return __half22float2(*reinterpret_cast<__half2*>(&u));
}
__device__ __forceinline__ float fsig(float v) {
    v = fminf(fmaxf(v, -15.f), 15.f);
    return 1.f / (1.f + __expf(-v));
}

// ---------------- prep kernels --------------------------------------------
__global__ void ln_kernel(const float* __restrict__ x,
                          const float* __restrict__ gamma,
                          const float* __restrict__ beta) {
    __shared__ float sred[16];
    __shared__ float s_mu, s_inv;
    int row = blockIdx.x, tid = threadIdx.x;
    const float4* xr = (const float4*)(x + (size_t)row * DM);
    float4 a = xr[tid], b = xr[tid + 256];
    float s = a.x + a.y + a.z + a.w + b.x + b.y + b.z + b.w;
    float q = a.x*a.x + a.y*a.y + a.z*a.z + a.w*a.w
            + b.x*b.x + b.y*b.y + b.z*b.z + b.w*b.w;
    for (int o = 16; o; o >>= 1) {
        s += __shfl_xor_sync(~0u, s, o);
        q += __shfl_xor_sync(~0u, q, o);
    }
    if ((tid & 31) == 0) { sred[tid >> 5] = s; sred[8 + (tid >> 5)] = q; }
    __syncthreads();
    if (tid == 0) {
        float S = 0.f, Q = 0.f;
        for (int i = 0; i < 8; i++) { S += sred[i]; Q += sred[8 + i]; }
        float mu = S / DM;
        s_mu = mu;
        s_inv = rsqrtf(Q / DM - mu * mu + 1e-5f);
    }
    __syncthreads();
    float mu = s_mu, inv = s_inv;
    float4 g0 = ((const float4*)gamma)[tid],       b0 = ((const float4*)beta)[tid];
    float4 g1 = ((const float4*)gamma)[tid + 256], b1 = ((const float4*)beta)[tid + 256];
    unsigned* dst = (unsigned*)(g_xn + (size_t)row * DM);
    float nx = (a.x - mu) * inv * g0.x + b0.x, ny = (a.y - mu) * inv * g0.y + b0.y;
    float nz = (a.z - mu) * inv * g0.z + b0.z, nw = (a.w - mu) * inv * g0.w + b0.w;
    dst[tid * 2]     = pk2h(nx, ny);
    dst[tid * 2 + 1] = pk2h(nz, nw);
    nx = (b.x - mu) * inv * g1.x + b1.x; ny = (b.y - mu) * inv * g1.y + b1.y;
    nz = (b.z - mu) * inv * g1.z + b1.z; nw = (b.w - mu) * inv * g1.w + b1.w;
    dst[(tid + 256) * 2]     = pk2h(nx, ny);
    dst[(tid + 256) * 2 + 1] = pk2h(nz, nw);
}

__global__ void cvt_kernel(const float* __restrict__ src, int which, int n4) {
    __half* dst = which ? g_win : g_wout;
    int i = blockIdx.x * blockDim.x + threadIdx.x;
    if (i < n4) {
        float4 f = ((const float4*)src)[i];
        uint2 o;
        o.x = pk2h(f.x, f.y);
        o.y = pk2h(f.z, f.w);
        ((uint2*)dst)[i] = o;
    }
}

__global__ void dts_kernel(const float* __restrict__ dt) {
    __shared__ float red[32];
    __shared__ float s_m, s_s;
    int tid = threadIdx.x;
    float m = -1e30f;
    for (int i = tid; i < DI; i += 1024) m = fmaxf(m, -dt[i]);
    for (int o = 16; o; o >>= 1) m = fmaxf(m, __shfl_xor_sync(~0u, m, o));
    if ((tid & 31) == 0) red[tid >> 5] = m;
    __syncthreads();
    if (tid == 0) {
        float M = -1e30f;
        for (int i = 0; i < 32; i++) M = fmaxf(M, red[i]);
        s_m = M;
    }
    __syncthreads();
    float M = s_m, s = 0.f;
    for (int i = tid; i < DI; i += 1024) s += __expf(-dt[i] - M);
    for (int o = 16; o; o >>= 1) s += __shfl_xor_sync(~0u, s, o);
    if ((tid & 31) == 0) red[tid >> 5] = s;
    __syncthreads();
    if (tid == 0) {
        float S = 0.f;
        for (int i = 0; i < 32; i++) S += red[i];
        s_s = S;
    }
    __syncthreads();
    float inv = 1.f / s_s;
    for (int i = tid; i < DI; i += 1024) g_dtw[i] = __expf(-dt[i] - M) * inv;
}

// ---------------- fp16 mma.sync GEMMs (fp16 accumulate) -------------------
// Stage = 32 KB (BK = 64 elems = 128 B rows, SW128):
//   FUSED:  A[128x64] @0 (16K), Bz[64x64] @16384 (8K), Bg[64x64] @24576 (8K)
//   !FUSED: A[128x64] @0 (16K), B[128x64] @16384 (16K)
// 3 stages = 96 KB -> 2 CTAs/SM. One __syncthreads per k-iter (stage-reuse
// ordering is carried by the next iteration's barrier).
#define NSTAGE 3
#define STAGEB 32768u

// FUSED=true : h[128 x 64] = 256 * z*sig(clamp z)*dtw * gc*sig(gc)  (fp16 out)
// FUSED=false: out[128 x 128] = (h @ W_out^T)/256 + x               (fp32 out)
template <bool FUSED>
__global__ void __launch_bounds__(256)
gemm_kernel(const float* __restrict__ xres, float* __restrict__ out) {
    extern __shared__ char smem[];
    const unsigned sbase = smem_u32(smem);
    __shared__ float s_dtw[64];

    const int tid = threadIdx.x, wid = tid >> 5, lane = tid & 31;
    const int wm = wid & 1;          // 2 warp-rows (64 M each)
    const int wn = wid >> 1;         // 4 warp-cols
    const int m0 = blockIdx.y * 128;
    const int n0 = blockIdx.x * (FUSED ? 64 : 128);
    const int KIT = FUSED ? (DM / 64) : (DI / 64);
    const int ldA = FUSED ? DM : DI;
    const __half* A  = FUSED ? g_xn : g_h;
    const __half* B0 = FUSED ? g_win : g_wout;
    const __half* B1 = g_win + (size_t)DI * DM;          // gate half of W_in

    if (FUSED && tid < 64) s_dtw[tid] = g_dtw[n0 + tid];

    // fp16 accumulators: 2 regs per m16n8 tile
    unsigned acc0[4][4][2];          // FUSED: z (nt 0-1) unused 2-3; !FUSED: 4 n-tiles
    unsigned acc1[4][2][2];          // FUSED: gate
    #pragma unroll
    for (int mt = 0; mt < 4; mt++) {
        #pragma unroll
        for (int nt = 0; nt < 4; nt++) { acc0[mt][nt][0] = 0u; acc0[mt][nt][1] = 0u; }
        #pragma unroll
        for (int nt = 0; nt < 2; nt++) { acc1[mt][nt][0] = 0u; acc1[mt][nt][1] = 0u; }
    }

    auto load_stage = [&](int s, int kb) {
        unsigned sb = sbase + (unsigned)s * STAGEB;
        int k0 = kb * 64;
        #pragma unroll
        for (int i = tid; i < 2048; i += 256) {
            if (FUSED) {
                if (i < 1024) {            // A: 128 rows x 8 chunks
                    int r = i >> 3, c = i & 7;
                    cp16(sb + SWZ(r * 128 + c * 16),
                         A + (size_t)(m0 + r) * ldA + k0 + c * 8);
                } else if (i < 1536) {     // Bz: 64 rows
                    int j = i - 1024, r = j >> 3, c = j & 7;
                    cp16(sb + 16384u + SWZ(r * 128 + c * 16),
                         B0 + (size_t)(n0 + r) * DM + k0 + c * 8);
                } else {                   // Bg: 64 rows
                    int j = i - 1536, r = j >> 3, c = j & 7;
                    cp16(sb + 24576u + SWZ(r * 128 + c * 16),
                         B1 + (size_t)(n0 + r) * DM + k0 + c * 8);
                }
            } else {
                if (i < 1024) {            // A (h): 128 rows
                    int r = i >> 3, c = i & 7;
                    cp16(sb + SWZ(r * 128 + c * 16),
                         A + (size_t)(m0 + r) * ldA + k0 + c * 8);
                } else {                   // B: 128 rows
                    int j = i - 1024, r = j >> 3, c = j & 7;
                    cp16(sb + 16384u + SWZ(r * 128 + c * 16),
                         B0 + (size_t)(n0 + r) * DI + k0 + c * 8);
                }
            }
        }
        CP_COMMIT();
    };

    load_stage(0, 0);
    load_stage(1, 1);

    // ldmatrix lane-address components (k-half select applied inside SWZ;
    // pre-swizzle offsets have bit4 == 0 so the +16 is carry-free)
    const int arow = (lane & 7) + (lane & 8);                 // A: 16 rows
    const unsigned acsel = (unsigned)(lane >> 4) << 4;        // A: k-half
    const int brow = (lane & 7) + ((lane >> 4) << 3);         // B: 16 rows (2 n-tiles)
    const unsigned bcsel = (unsigned)((lane >> 3) & 1) << 4;  // B: k-half

    for (int kb = 0; kb < KIT; kb++) {
        if (kb == KIT - 1) { CP_WAIT(0); } else { CP_WAIT(1); }
        __syncthreads();
        if (kb + 2 < KIT) load_stage((kb + 2) % NSTAGE, kb + 2);

        unsigned sb = sbase + (unsigned)(kb % NSTAGE) * STAGEB;
        unsigned sBz = sb + 16384u;
        unsigned sBg = sb + 24576u;
        #pragma unroll
        for (int kc = 0; kc < 4; kc++) {
            unsigned a[4][4];
            #pragma unroll
            for (int mt = 0; mt < 4; mt++)
                ldsm4(a[mt], sb + SWZ((unsigned)((wm * 64 + mt * 16 + arow) * 128
                                                 + kc * 32) + acsel));
            if (FUSED) {
                // one 16-row ldsm4 each for z and gate (2 n-tiles x 2 k-halves)
                unsigned bz[4], bg[4];
                unsigned roff = (unsigned)((wn * 16 + brow) * 128 + kc * 32);
                ldsm4(bz, sBz + SWZ(roff + bcsel));
                ldsm4(bg, sBg + SWZ(roff + bcsel));
                #pragma unroll
                for (int mt = 0; mt < 4; mt++) {
                    mma16816h(acc0[mt][0], a[mt], bz[0], bz[1]);
                    mma16816h(acc0[mt][1], a[mt], bz[2], bz[3]);
                    mma16816h(acc1[mt][0], a[mt], bg[0], bg[1]);
                    mma16816h(acc1[mt][1], a[mt], bg[2], bg[3]);
                }
            } else {
                unsigned bq[2][4];
                #pragma unroll
                for (int p = 0; p < 2; p++)
                    ldsm4(bq[p], sBz + SWZ((unsigned)((wn * 32 + p * 16 + brow) * 128
                                                      + kc * 32) + bcsel));
                #pragma unroll
                for (int mt = 0; mt < 4; mt++)
                    #pragma unroll
                    for (int p = 0; p < 2; p++) {
                        mma16816h(acc0[mt][p * 2],     a[mt], bq[p][0], bq[p][1]);
                        mma16816h(acc0[mt][p * 2 + 1], a[mt], bq[p][2], bq[p][3]);
                    }
            }
        }
    }

    // ---------------- epilogue ---------------------------------------------
    const int mrow = (lane >> 2);
    const int ncol = (lane & 3) * 2;
    if (FUSED) {
        #pragma unroll
        for (int mt = 0; mt < 4; mt++)
            #pragma unroll
            for (int nt = 0; nt < 2; nt++) {
                int nl = wn * 16 + nt * 8 + ncol;
                float w0 = s_dtw[nl] * HSCALE, w1 = s_dtw[nl + 1] * HSCALE;
                #pragma unroll
                for (int h = 0; h < 2; h++) {
                    int m = m0 + wm * 64 + mt * 16 + mrow + h * 8;
                    float2 zv = up2h(acc0[mt][nt][h]);
                    float2 gv = up2h(acc1[mt][nt][h]);
                    float gc0 = fminf(fmaxf(gv.x, -15.f), 15.f);
                    float gc1 = fminf(fmaxf(gv.y, -15.f), 15.f);
                    float v0 = zv.x * fsig(zv.x) * w0 * gc0 * fsig(gc0);
                    float v1 = zv.y * fsig(zv.y) * w1 * gc1 * fsig(gc1);
                    *(unsigned*)(g_h + (size_t)m * DI + n0 + nl) = pk2h(v0, v1);
                }
            }
    } else {
        #pragma unroll
        for (int mt = 0; mt < 4; mt++)
            #pragma unroll
            for (int nt = 0; nt < 4; nt++) {
                int n = n0 + wn * 32 + nt * 8 + ncol;
                #pragma unroll
                for (int h = 0; h < 2; h++) {
                    int m = m0 + wm * 64 + mt * 16 + mrow + h * 8;
                    const float2 xv = *(const float2*)(xres + (size_t)m * DM + n);
                    float2 cv = up2h(acc0[mt][nt][h]);
                    float2 o;
                    o.x = cv.x * HINV + xv.x;
                    o.y = cv.y * HINV + xv.y;
                    *(float2*)(out + (size_t)m * DM + n) = o;
                }
            }
    }
}

// ---------------- launch ----------------------------------------------------
extern "C" void kernel_launch(void* const* d_in, const int* in_sizes, int n_in,
                              void* d_out, int out_size) {
    const float* x     = (const float*)d_in[0];
    const float* gamma = (const float*)d_in[1];
    const float* beta  = (const float*)d_in[2];
    const float* W_in  = (const float*)d_in[3];
    const float* W_out = (const float*)d_in[4];
    const float* dt    = (const float*)d_in[5];
    float* out = (float*)d_out;

    ln_kernel<<<MTOT, 256>>>(x, gamma, beta);
    {
        int n4 = 2 * DI * DM / 4;
        cvt_kernel<<<(n4 + 255) / 256, 256>>>(W_in, 1, n4);
    }
    {
        int n4 = DM * DI / 4;
        cvt_kernel<<<(n4 + 255) / 256, 256>>>(W_out, 0, n4);
    }
    dts_kernel<<<1, 1024>>>(dt);

    const unsigned smem = NSTAGE * STAGEB;   // 96 KB
    static int attr_done = 0;                 // never during graph capture
    if (!attr_done) {
        cudaFuncSetAttribute(gemm_kernel<true>,
                             cudaFuncAttributeMaxDynamicSharedMemorySize, smem);
        cudaFuncSetAttribute(gemm_kernel<false>,
                             cudaFuncAttributeMaxDynamicSharedMemorySize, smem);
        attr_done = 1;
    }

    gemm_kernel<true ><<<dim3(DI / 64, MTOT / 128), 256, smem>>>(nullptr, nullptr);
    gemm_kernel<false><<<dim3(DM / 128, MTOT / 128), 256, smem>>>(x, out);
}